// round 2
// baseline (speedup 1.0000x reference)
#include <cuda_runtime.h>

#define N_WIRES 4
#define N_LAYERS 3
#define BATCH 65536
#define BN_EPS 1e-5f
#define TPB 256
#define SPB 256   // samples per block
#define PIX 784
#define CHUNK 196

// ---- device scratch (no allocations allowed) ----
__device__ float2 g_M[N_LAYERS][N_WIRES][4];   // fused RX@RZ, row-major 2x2
__device__ double g_sum[4];
__device__ double g_sumsq[4];
__device__ float  g_scale[4];
__device__ float  g_shift[4];

__device__ __forceinline__ float2 cmul(float2 a, float2 b) {
    return make_float2(a.x * b.x - a.y * b.y, a.x * b.y + a.y * b.x);
}
__device__ __forceinline__ float2 cadd(float2 a, float2 b) {
    return make_float2(a.x + b.x, a.y + b.y);
}

// Apply 2x2 gate on qubit with stride D (compile-time), 16-amp statevector in regs.
template <int D>
__device__ __forceinline__ void apply_gate(float2 s[16], float2 U00, float2 U01,
                                           float2 U10, float2 U11) {
#pragma unroll
    for (int i = 0; i < 16; ++i) {
        if (i & D) continue;
        float2 a = s[i];
        float2 b = s[i | D];
        s[i]     = cadd(cmul(U00, a), cmul(U01, b));
        s[i | D] = cadd(cmul(U10, a), cmul(U11, b));
    }
}

// CNOT: control bit C, target bit T (compile-time strides)
template <int C, int T>
__device__ __forceinline__ void cnot(float2 s[16]) {
#pragma unroll
    for (int i = 0; i < 16; ++i) {
        if (!(i & C) || (i & T)) continue;
        float2 t = s[i];
        s[i] = s[i | T];
        s[i | T] = t;
    }
}

// U = M @ RY(c, s) ; RY = [[c,-s],[s,c]] (real)
template <int D>
__device__ __forceinline__ void do_wire(float2 st[16], const float2* __restrict__ M,
                                        float c, float s) {
    float2 M0 = M[0], M1 = M[1], M2 = M[2], M3 = M[3];
    float2 U00 = make_float2(M0.x * c + M1.x * s, M0.y * c + M1.y * s);
    float2 U01 = make_float2(M1.x * c - M0.x * s, M1.y * c - M0.y * s);
    float2 U10 = make_float2(M2.x * c + M3.x * s, M2.y * c + M3.y * s);
    float2 U11 = make_float2(M3.x * c - M2.x * s, M3.y * c - M2.y * s);
    apply_gate<D>(st, U00, U01, U10, U11);
}

// ---- kernel 0: zero accumulators + precompute fused gates ----
__global__ void init_kernel(const float* __restrict__ params) {
    int t = threadIdx.x;
    if (t < 4) { g_sum[t] = 0.0; g_sumsq[t] = 0.0; }
    if (t < N_LAYERS * N_WIRES) {
        int l = t / N_WIRES, w = t % N_WIRES;
        float t0 = params[t * 3 + 0];
        float t1 = params[t * 3 + 1];
        float s0, c0, s1, c1;
        sincosf(0.5f * t0, &s0, &c0);
        sincosf(0.5f * t1, &s1, &c1);
        // M = RX(t1) @ RZ(t0):
        // M00 = c1*e^{-i t0/2}, M01 = -i s1 * e^{+i t0/2}
        // M10 = -i s1 * e^{-i t0/2}, M11 = c1*e^{+i t0/2}
        g_M[l][w][0] = make_float2(c1 * c0, -c1 * s0);
        g_M[l][w][1] = make_float2(s1 * s0, -s1 * c0);
        g_M[l][w][2] = make_float2(-s1 * s0, -s1 * c0);
        g_M[l][w][3] = make_float2(c1 * c0, c1 * s0);
    }
}

// ---- kernel 1: encode + simulate + linear + partial BN stats ----
__global__ __launch_bounds__(TPB) void sim_kernel(const float* __restrict__ x,
                                                  const float* __restrict__ W,
                                                  const float* __restrict__ b,
                                                  float4* __restrict__ out) {
    __shared__ float s_enc[SPB][4];
    __shared__ float s_red[8][8];

    const int tid = threadIdx.x;
    const int wrp = tid >> 5;
    const int lane = tid & 31;
    const long long blockBase = (long long)blockIdx.x * SPB;

    // -------- phase 1: warp-per-sample chunk means (coalesced) --------
    for (int it = 0; it < SPB / 8; ++it) {
        int sl = wrp * (SPB / 8) + it;                  // local sample 0..255
        const float* px = x + (blockBase + sl) * PIX;
#pragma unroll
        for (int c = 0; c < 4; ++c) {
            const float* pc = px + CHUNK * c;
            float v = 0.f;
#pragma unroll
            for (int k = 0; k < 6; ++k) v += pc[lane + 32 * k];
            if (lane < 4) v += pc[192 + lane];
#pragma unroll
            for (int o = 16; o; o >>= 1) v += __shfl_xor_sync(0xffffffffu, v, o);
            if (lane == 0) s_enc[sl][c] = v * (1.0f / 196.0f);
        }
    }
    __syncthreads();

    // -------- phase 2: one thread = one sample, statevector in registers --------
    float cw[4], sw[4];
#pragma unroll
    for (int w = 0; w < 4; ++w) sincosf(0.5f * s_enc[tid][w], &sw[w], &cw[w]);

    float2 st[16];
#pragma unroll
    for (int i = 0; i < 16; ++i) st[i] = make_float2(0.f, 0.f);
    st[0] = make_float2(1.f, 0.f);

#pragma unroll
    for (int l = 0; l < N_LAYERS; ++l) {
        do_wire<1>(st, g_M[l][0], cw[0], sw[0]);
        cnot<1, 2>(st);
        do_wire<2>(st, g_M[l][1], cw[1], sw[1]);
        cnot<2, 4>(st);
        do_wire<4>(st, g_M[l][2], cw[2], sw[2]);
        cnot<4, 8>(st);
        do_wire<8>(st, g_M[l][3], cw[3], sw[3]);
    }

    float z[4] = {0.f, 0.f, 0.f, 0.f};
#pragma unroll
    for (int i = 0; i < 16; ++i) {
        float p = st[i].x * st[i].x + st[i].y * st[i].y;
        z[0] += (i & 1) ? -p : p;
        z[1] += (i & 2) ? -p : p;
        z[2] += (i & 4) ? -p : p;
        z[3] += (i & 8) ? -p : p;
    }

    // Linear(4,4): out[j] = b[j] + sum_w z[w] * W[j*4+w]
    float o[4];
#pragma unroll
    for (int j = 0; j < 4; ++j) {
        float acc = b[j];
#pragma unroll
        for (int w = 0; w < 4; ++w) acc += z[w] * W[j * 4 + w];
        o[j] = acc;
    }
    out[blockBase + tid] = make_float4(o[0], o[1], o[2], o[3]);

    // -------- BN partial sums --------
    float red[8] = {o[0], o[1], o[2], o[3],
                    o[0] * o[0], o[1] * o[1], o[2] * o[2], o[3] * o[3]};
#pragma unroll
    for (int k = 0; k < 8; ++k) {
        float v = red[k];
#pragma unroll
        for (int off = 16; off; off >>= 1) v += __shfl_xor_sync(0xffffffffu, v, off);
        red[k] = v;
    }
    if (lane == 0) {
#pragma unroll
        for (int k = 0; k < 8; ++k) s_red[wrp][k] = red[k];
    }
    __syncthreads();
    if (tid < 8) {
        float v = 0.f;
#pragma unroll
        for (int w = 0; w < 8; ++w) v += s_red[w][tid];
        if (tid < 4) atomicAdd(&g_sum[tid], (double)v);
        else         atomicAdd(&g_sumsq[tid - 4], (double)v);
    }
}

// ---- kernel 2: fold stats into scale/shift ----
__global__ void stats_kernel(const float* __restrict__ bn_w,
                             const float* __restrict__ bn_b) {
    int j = threadIdx.x;
    if (j < 4) {
        float mu  = (float)(g_sum[j]   * (1.0 / BATCH));
        float ex2 = (float)(g_sumsq[j] * (1.0 / BATCH));
        float var = ex2 - mu * mu;
        float sc = bn_w[j] * rsqrtf(var + BN_EPS);
        g_scale[j] = sc;
        g_shift[j] = bn_b[j] - mu * sc;
    }
}

// ---- kernel 3: in-place batchnorm on d_out ----
__global__ __launch_bounds__(256) void bn_kernel(float4* __restrict__ out) {
    int i = blockIdx.x * blockDim.x + threadIdx.x;
    if (i < BATCH) {
        float4 v = out[i];
        v.x = v.x * g_scale[0] + g_shift[0];
        v.y = v.y * g_scale[1] + g_shift[1];
        v.z = v.z * g_scale[2] + g_shift[2];
        v.w = v.w * g_scale[3] + g_shift[3];
        out[i] = v;
    }
}

extern "C" void kernel_launch(void* const* d_in, const int* in_sizes, int n_in,
                              void* d_out, int out_size) {
    const float* x      = (const float*)d_in[0];
    const float* params = (const float*)d_in[1];
    const float* W      = (const float*)d_in[2];
    const float* b      = (const float*)d_in[3];
    const float* bn_w   = (const float*)d_in[4];
    const float* bn_b   = (const float*)d_in[5];
    float4* out = (float4*)d_out;

    init_kernel<<<1, 64>>>(params);
    sim_kernel<<<BATCH / SPB, TPB>>>(x, W, b, out);
    stats_kernel<<<1, 32>>>(bn_w, bn_b);
    bn_kernel<<<BATCH / 256, 256>>>(out);
}